// round 9
// baseline (speedup 1.0000x reference)
#include <cuda_runtime.h>
#include <math.h>

#define BSZ   256
#define ISIZE 256
#define HSIZE 512
#define BH    (BSZ*HSIZE)
#define BK 16

#define NGATE  384            // 3 regions (x, hA, hB) x 4 gates x 32 tiles
#define NP1    (NGATE + 512)  // phase-1 slots: gates + 512 reduce units
#define GRID1  296            // 2 CTAs/SM x 148 SMs -> all co-resident

// Scratch (device globals)
__device__ __align__(16) float g_prex[4*BH];    // x-side gate partials
__device__ __align__(16) float g_preh0[4*BH];   // h-side partials, K rows 0..255
__device__ __align__(16) float g_preh1[4*BH];   // h-side partials, K rows 256..511
__device__ __align__(16) float g_hredp[8*BH];   // hred partials (2 halves x 4 groups)
__device__ __align__(16) float g_ei[BH];        // eta*its per (b,k)
__device__ int g_bar1, g_bar2;                  // grid barrier counters

__global__ void kzero() { g_bar1 = 0; g_bar2 = 0; }

// ---------------------------------------------------------------------------
// KMAIN: one persistent kernel, 296 CTAs x 512 threads.
//  P1: gates (slots 0..383) + barrier-free streaming reduce (384..895)
//  -- grid barrier --
//  P2: per-batch cell/hact/m/ei (256 units)
//  -- grid barrier --
//  P3: hebb update in REVERSE unit order; __ldcs reads (hit L2 residue from
//      P1 tail), __stcs writes (don't thrash L2).
// ---------------------------------------------------------------------------
__global__ __launch_bounds__(512, 2)
void kmain(const float* __restrict__ x, const float* __restrict__ h0,
           const float* __restrict__ hebb, const float* __restrict__ c0,
           const float* __restrict__ alpha,
           const float* __restrict__ x2f, const float* __restrict__ x2i,
           const float* __restrict__ x2o, const float* __restrict__ x2c,
           const float* __restrict__ h2f, const float* __restrict__ h2i,
           const float* __restrict__ h2o, const float* __restrict__ w,
           const float* __restrict__ x2f_b, const float* __restrict__ h2f_b,
           const float* __restrict__ x2i_b, const float* __restrict__ h2i_b,
           const float* __restrict__ x2o_b, const float* __restrict__ h2o_b,
           const float* __restrict__ x2c_b,
           const float* __restrict__ h2mod_w, const float* __restrict__ h2mod_b,
           const float* __restrict__ mfw, const float* __restrict__ mfb,
           float* __restrict__ out_hact, float* __restrict__ out_cell,
           float* __restrict__ out_hebb)
{
    __shared__ union {
        struct { float As[BK][68]; float Ws[BK][68]; } t;   // gate tiles
        struct { float sred[16]; float smv; } m;            // phase-2 reduce
    } sm;

    int tid = threadIdx.x;
    int bid = blockIdx.x;

    // ======================= PHASE 1: gates + reduce =======================
    for (int s = bid; s < NP1; s += GRID1) {
        if (s >= NGATE) {
            // ---- reduce unit (b, half): barrier-free, 8 global partials ---
            int ru = s - NGATE;
            int b = ru >> 1;
            int half = ru & 1;
            int g = tid >> 7;              // row-group 0..3 (64 rows)
            int c = tid & 127;             // f4 column
            int hbase = half * 256 + g * 64;
            const float4* hb4 = (const float4*)(hebb + (size_t)b * HSIZE * HSIZE)
                                + (size_t)hbase * 128 + c;
            const float* h0p = h0 + b * HSIZE + hbase;
            float4 acc = make_float4(0.f, 0.f, 0.f, 0.f);
#pragma unroll 8
            for (int i = 0; i < 64; ++i) {
                float sv = __ldg(h0p + i);
                float4 v = hb4[(size_t)i * 128];
                acc.x = fmaf(sv, v.x, acc.x);
                acc.y = fmaf(sv, v.y, acc.y);
                acc.z = fmaf(sv, v.z, acc.z);
                acc.w = fmaf(sv, v.w, acc.w);
            }
            int p = half * 4 + g;
            ((float4*)(g_hredp + (size_t)p * BH + b * HSIZE))[c] = acc;
        } else {
            // ---- gate GEMM unit (16 k-tiles) ------------------------------
            int region = s >> 7;           // 0=x, 1=h rows 0..255, 2=h rows 256..511
            int r = s & 127;
            int gate = r >> 5;
            int ct = r & 31;
            int bn0 = (ct & 7) * 64;
            int bm0 = (ct >> 3) * 64;
            const float* A = region ? h0 : x;
            int KA = region ? HSIZE : ISIZE;
            int kbeg = (region == 2) ? 256 : 0;
            const float* W;
            if (region == 0)
                W = (gate == 0) ? x2f : (gate == 1) ? x2i : (gate == 2) ? x2o : x2c;
            else
                W = (gate == 0) ? h2f : (gate == 1) ? h2i : (gate == 2) ? h2o : w;
            bool trans = (region >= 1) && (gate == 3);   // w is [h,k]

            int tx = tid & 15, ty = tid >> 4;
            float acc[2][4] = {};

            for (int kt = 0; kt < 16; ++kt) {
                int k0 = kbeg + kt * BK;
#pragma unroll
                for (int l = 0; l < 2; l++) {
                    int e = tid + l * 512; int rr = e >> 4; int cc = e & 15;
                    sm.t.As[cc][rr] = A[(size_t)(bm0 + rr) * KA + k0 + cc];
                }
                if (trans) {
#pragma unroll
                    for (int l = 0; l < 2; l++) {
                        int e = tid + l * 512; int rr = e & 63; int cc = e >> 6;
                        sm.t.Ws[cc][rr] = W[(size_t)(k0 + cc) * HSIZE + bn0 + rr];
                    }
                } else {
#pragma unroll
                    for (int l = 0; l < 2; l++) {
                        int e = tid + l * 512; int rr = e >> 4; int cc = e & 15;
                        sm.t.Ws[cc][rr] = W[(size_t)(bn0 + rr) * KA + k0 + cc];
                    }
                }
                __syncthreads();
#pragma unroll
                for (int kb = 0; kb < BK; kb++) {
                    float2 ra = *(const float2*)&sm.t.As[kb][ty * 2];
                    float4 rb = *(const float4*)&sm.t.Ws[kb][tx * 4];
                    float a[2] = {ra.x, ra.y};
                    float bv[4] = {rb.x, rb.y, rb.z, rb.w};
#pragma unroll
                    for (int i = 0; i < 2; i++)
#pragma unroll
                        for (int j = 0; j < 4; j++)
                            acc[i][j] = fmaf(a[i], bv[j], acc[i][j]);
                }
                __syncthreads();
            }
            float* outb = (region == 0 ? g_prex : region == 1 ? g_preh0 : g_preh1)
                        + (size_t)gate * BH;
#pragma unroll
            for (int i = 0; i < 2; i++) {
                int bb = bm0 + ty * 2 + i;
#pragma unroll
                for (int j = 0; j < 4; j++)
                    outb[(size_t)bb * HSIZE + bn0 + tx * 4 + j] = acc[i][j];
            }
        }
    }

    // ======================= grid barrier 1 ================================
    __threadfence();
    __syncthreads();
    if (tid == 0) {
        atomicAdd(&g_bar1, 1);
        while (*(volatile int*)&g_bar1 != GRID1) __nanosleep(64);
        __threadfence();
    }
    __syncthreads();

    // ======================= PHASE 2: per-batch math =======================
    for (int b = bid; b < BSZ; b += GRID1) {
        int k = tid;
        int idx = b * HSIZE + k;
        float hred = 0.f;
#pragma unroll
        for (int p = 0; p < 8; p++) hred += g_hredp[(size_t)p * BH + idx];

        float pf = g_prex[idx]          + g_preh0[idx]          + g_preh1[idx]
                 + x2f_b[k] + h2f_b[k];
        float pi = g_prex[BH + idx]     + g_preh0[BH + idx]     + g_preh1[BH + idx]
                 + x2i_b[k] + h2i_b[k];
        float po = g_prex[2 * BH + idx] + g_preh0[2 * BH + idx] + g_preh1[2 * BH + idx]
                 + x2o_b[k] + h2o_b[k];
        float pc = g_prex[3 * BH + idx] + g_preh0[3 * BH + idx] + g_preh1[3 * BH + idx]
                 + x2c_b[k] + alpha[k] * hred;
        float fgt = 1.f / (1.f + expf(-pf));
        float ipt = 1.f / (1.f + expf(-pi));
        float opt = 1.f / (1.f + expf(-po));
        float its = tanhf(pc);
        float cell = fgt * c0[idx] + ipt * its;
        float hact = opt * tanhf(cell);
        out_cell[idx] = cell;
        out_hact[idx] = hact;

        float mv = hact * h2mod_w[k];
#pragma unroll
        for (int o = 16; o > 0; o >>= 1)
            mv += __shfl_down_sync(0xffffffffu, mv, o);
        if ((k & 31) == 0) sm.m.sred[k >> 5] = mv;
        __syncthreads();
        if (k == 0) {
            float t2 = 0.f;
#pragma unroll
            for (int i = 0; i < 16; i++) t2 += sm.m.sred[i];
            sm.m.smv = tanhf(t2 + h2mod_b[0]);
        }
        __syncthreads();
        g_ei[idx] = fmaf(sm.m.smv, mfw[k], mfb[k]) * its;
        __syncthreads();
    }

    // ======================= grid barrier 2 ================================
    __threadfence();
    __syncthreads();
    if (tid == 0) {
        atomicAdd(&g_bar2, 1);
        while (*(volatile int*)&g_bar2 != GRID1) __nanosleep(64);
        __threadfence();
    }
    __syncthreads();

    // ======================= PHASE 3: hebb update ==========================
    // Reverse unit order vs phase 1 -> L2-resident tail is re-read first.
    for (int s = bid; s < 512; s += GRID1) {
        int ru = 511 - s;
        int b = ru >> 1;
        int half = ru & 1;
        int g = tid >> 7;
        int c = tid & 127;
        int hbase = half * 256 + g * 64;
        const float4* hb4 = (const float4*)(hebb + (size_t)b * HSIZE * HSIZE)
                            + (size_t)hbase * 128 + c;
        float4* ob4 = (float4*)(out_hebb + (size_t)b * HSIZE * HSIZE)
                      + (size_t)hbase * 128 + c;
        const float* h0p = h0 + b * HSIZE + hbase;
        float4 e4 = ((const float4*)g_ei)[b * 128 + c];
#pragma unroll 4
        for (int i = 0; i < 64; ++i) {
            float sv = __ldg(h0p + i);
            float4 v = __ldcs(hb4 + (size_t)i * 128);
            float4 o;
            float t;
            t = fmaf(sv, e4.x, v.x); o.x = fminf(fmaxf(t, -2.f), 2.f);
            t = fmaf(sv, e4.y, v.y); o.y = fminf(fmaxf(t, -2.f), 2.f);
            t = fmaf(sv, e4.z, v.z); o.z = fminf(fmaxf(t, -2.f), 2.f);
            t = fmaf(sv, e4.w, v.w); o.w = fminf(fmaxf(t, -2.f), 2.f);
            __stcs(ob4 + (size_t)i * 128, o);
        }
    }
}

// ---------------------------------------------------------------------------
extern "C" void kernel_launch(void* const* d_in, const int* in_sizes, int n_in,
                              void* d_out, int out_size)
{
    const float* inputs  = (const float*)d_in[0];
    const float* h0      = (const float*)d_in[1];
    const float* c0      = (const float*)d_in[2];
    const float* hebb    = (const float*)d_in[3];
    const float* w       = (const float*)d_in[4];
    const float* alpha   = (const float*)d_in[5];
    const float* h2f_w   = (const float*)d_in[6];
    const float* h2f_b   = (const float*)d_in[7];
    const float* h2i_w   = (const float*)d_in[8];
    const float* h2i_b   = (const float*)d_in[9];
    const float* h2o_w   = (const float*)d_in[10];
    const float* h2o_b   = (const float*)d_in[11];
    const float* x2f_w   = (const float*)d_in[12];
    const float* x2f_b   = (const float*)d_in[13];
    const float* x2i_w   = (const float*)d_in[14];
    const float* x2i_b   = (const float*)d_in[15];
    const float* x2o_w   = (const float*)d_in[16];
    const float* x2o_b   = (const float*)d_in[17];
    const float* x2c_w   = (const float*)d_in[18];
    const float* x2c_b   = (const float*)d_in[19];
    const float* h2mod_w = (const float*)d_in[20];
    const float* h2mod_b = (const float*)d_in[21];
    const float* mfw     = (const float*)d_in[22];
    const float* mfb     = (const float*)d_in[23];

    float* out       = (float*)d_out;
    float* out_hact  = out;              // [B,H]
    float* out_cell  = out + BH;         // [B,H]
    float* out_hebb  = out + 2 * BH;     // [B,H,H]

    kzero<<<1, 1>>>();

    kmain<<<GRID1, 512>>>(inputs, h0, hebb, c0, alpha,
                          x2f_w, x2i_w, x2o_w, x2c_w,
                          h2f_w, h2i_w, h2o_w, w,
                          x2f_b, h2f_b, x2i_b, h2i_b, x2o_b, h2o_b, x2c_b,
                          h2mod_w, h2mod_b, mfw, mfb,
                          out_hact, out_cell, out_hebb);
}